// round 1
// baseline (speedup 1.0000x reference)
#include <cuda_runtime.h>
#include <math.h>

#define Mdim 512
#define Ndim 2048
#define Bsz  4
#define Lnum 20
#define CAP  24576           // >= 25 sigma above E[nnz]=20971
#define MNdim (Mdim*Ndim)
#define EPSV 1e-6f
#define NTH  1024

// ---------------- device scratch (no allocations allowed) ----------------
__device__ int      g_deg[Mdim];
__device__ int      g_rowptr[Mdim + 1];
__device__ int      g_nnz;
__device__ unsigned g_lin[CAP];          // linear index i*N+j per nonzero (row-major CSR order)
__device__ float    g_wde[Lnum * CAP];   // gathered weights_de
__device__ float    g_mwde[Lnum * CAP];  // gathered marg_weights_de
__device__ float    g_rho[Lnum];         // softmax(rhos)

// ---------------- K0: zero output + softmax(rhos) ----------------
__global__ void k_init(const float* __restrict__ rhos, float* __restrict__ out) {
    if (threadIdx.x == 0) {
        *out = 0.0f;
        float mx = -1e30f;
        for (int l = 0; l < Lnum; l++) mx = fmaxf(mx, rhos[l]);
        float e[Lnum], s = 0.0f;
        for (int l = 0; l < Lnum; l++) { e[l] = expf(rhos[l] - mx); s += e[l]; }
        float inv = 1.0f / s;
        for (int l = 0; l < Lnum; l++) g_rho[l] = e[l] * inv;
    }
}

// ---------------- K1: row degrees (block per row) ----------------
__global__ void k_deg(const float* __restrict__ H) {
    __shared__ int red[8];
    int i = blockIdx.x;
    int cnt = 0;
    for (int c = threadIdx.x; c < Ndim; c += 256)
        cnt += (H[i * Ndim + c] != 0.0f);
    for (int o = 16; o; o >>= 1) cnt += __shfl_xor_sync(0xffffffffu, cnt, o);
    if ((threadIdx.x & 31) == 0) red[threadIdx.x >> 5] = cnt;
    __syncthreads();
    if (threadIdx.x == 0) {
        int s = 0;
        for (int w = 0; w < 8; w++) s += red[w];
        g_deg[i] = s;
    }
}

// ---------------- K2: exclusive prefix scan over 512 degrees ----------------
__global__ void k_scan() {
    __shared__ int s[Mdim];
    int t = threadIdx.x;
    if (t < Mdim) s[t] = g_deg[t];
    __syncthreads();
    for (int off = 1; off < Mdim; off <<= 1) {
        int v = 0;
        if (t < Mdim && t >= off) v = s[t - off];
        __syncthreads();
        if (t < Mdim) s[t] += v;
        __syncthreads();
    }
    if (t < Mdim) g_rowptr[t + 1] = s[t];
    if (t == 0) g_rowptr[0] = 0;
    if (t == Mdim - 1) g_nnz = s[Mdim - 1];
}

// ---------------- K3: fill CSR column indices (warp per row) ----------------
__global__ void k_fill(const float* __restrict__ H) {
    int w = (blockIdx.x * blockDim.x + threadIdx.x) >> 5;
    int lane = threadIdx.x & 31;
    if (w >= Mdim) return;
    int base = g_rowptr[w];
    for (int c0 = 0; c0 < Ndim; c0 += 32) {
        int c = c0 + lane;
        float v = H[w * Ndim + c];
        unsigned m = __ballot_sync(0xffffffffu, v != 0.0f);
        if (v != 0.0f) {
            int p = __popc(m & ((1u << lane) - 1u));
            int idx = base + p;
            if (idx < CAP) g_lin[idx] = (unsigned)(w * Ndim + c);
        }
        base += __popc(m);
    }
}

// ---------------- K4: gather dense weights at nonzeros ----------------
__global__ void k_gather(const float* __restrict__ wde, const float* __restrict__ mwde) {
    int nnz = min(g_nnz, CAP);
    int idx = blockIdx.x * blockDim.x + threadIdx.x;
    if (idx >= Lnum * CAP) return;
    int l = idx / CAP;
    int k = idx - l * CAP;
    if (k < nnz) {
        unsigned lin = g_lin[k];
        size_t off = (size_t)l * MNdim + lin;
        g_wde[idx]  = wde[off];
        g_mwde[idx] = mwde[off];
    }
}

// ---------------- K5: main BP recurrence, one block per batch ----------------
// smem layout (bytes): msgs CAP*4 | lin CAP*4 | col N*4 | bel N*4 | rp M*4 |
//                      sign M*4 | off M*4 | rpt (M+4)*4 | err N*4 | red 32*4
#define SMEM_BYTES ((CAP*2 + Ndim*3 + Mdim*3 + (Mdim+4) + 32) * 4)

__global__ void __launch_bounds__(NTH, 1) k_main(
    const int*   __restrict__ synd,
    const int*   __restrict__ errs,
    const float* __restrict__ llrs,
    const float* __restrict__ wllr,
    const float* __restrict__ mwllr,
    const float* __restrict__ resw,
    float* __restrict__ out)
{
    extern __shared__ char sm_raw[];
    float*    s_msgs = (float*)sm_raw;                  // CAP
    unsigned* s_lin  = (unsigned*)(s_msgs + CAP);       // CAP
    float*    s_col  = (float*)(s_lin + CAP);           // N
    float*    s_bel  = s_col + Ndim;                    // N
    float*    s_rp   = s_bel + Ndim;                    // M
    float*    s_sign = s_rp + Mdim;                     // M
    float*    s_off  = s_sign + Mdim;                   // M
    int*      s_rpt  = (int*)(s_off + Mdim);            // M+4
    float*    s_err  = (float*)(s_rpt + Mdim + 4);      // N
    float*    s_red  = s_err + Ndim;                    // 32

    const int tid = threadIdx.x;
    const int b = blockIdx.x;
    const int lane = tid & 31;
    const int wid = tid >> 5;
    const int nnz = min(g_nnz, CAP);
    const float one_m_eps = 1.0f - EPSV;

    // ---- preload ----
    for (int k = tid; k < nnz; k += NTH) { s_lin[k] = g_lin[k]; s_msgs[k] = 0.0f; }
    for (int j = tid; j < Ndim; j += NTH) s_err[j] = 1.0f - (float)errs[b * Ndim + j];
    if (tid < Mdim) {
        s_sign[tid] = 1.0f - 2.0f * (float)synd[b * Mdim + tid];
        int d = g_rowptr[tid + 1] - g_rowptr[tid];
        s_off[tid] = powf(one_m_eps, (float)(Ndim - d));  // off-support clip factor
    }
    if (tid <= Mdim) s_rpt[tid] = g_rowptr[tid];
    __syncthreads();

    float acc = 0.0f;
    for (int l = 0; l < Lnum; l++) {
        const float* wde  = &g_wde[l * CAP];
        const float* mwde = &g_mwde[l * CAP];
        const float rw = resw[l];

        // phase 1: column sums of msgs*w_de, plus llr*w_llr term
        for (int j = tid; j < Ndim; j += NTH) s_col[j] = 0.0f;
        __syncthreads();
        for (int k = tid; k < nnz; k += NTH)
            atomicAdd(&s_col[s_lin[k] & (Ndim - 1)], s_msgs[k] * wde[k]);
        __syncthreads();
        for (int j = tid; j < Ndim; j += NTH)
            s_col[j] += llrs[j] * wllr[l * Ndim + j];
        __syncthreads();

        // phase 2: row products of clipped tanh (warp per row)
        for (int i = wid; i < Mdim; i += 32) {
            int st = s_rpt[i], en = s_rpt[i + 1];
            float p = 1.0f;
            for (int k = st + lane; k < en; k += 32) {
                float men = s_col[s_lin[k] & (Ndim - 1)] - s_msgs[k];
                float d = tanhf(0.5f * men);
                if (d == 0.0f) d = 1.0f;
                d = fminf(fmaxf(d, -one_m_eps), one_m_eps);
                p *= d;
            }
            for (int o = 16; o; o >>= 1) p *= __shfl_xor_sync(0xffffffffu, p, o);
            if (lane == 0) s_rp[i] = p * s_off[i];
        }
        // phase 3 init: beliefs = llr*mw_llr
        for (int j = tid; j < Ndim; j += NTH)
            s_bel[j] = llrs[j] * mwllr[l * Ndim + j];
        __syncthreads();  // row products + belief init complete

        // phase 3: message update + belief column reduce
        for (int k = tid; k < nnz; k += NTH) {
            unsigned lin = s_lin[k];
            int j = lin & (Ndim - 1);
            int i = lin >> 11;
            float men = s_col[j] - s_msgs[k];
            float d = tanhf(0.5f * men);
            if (d == 0.0f) d = 1.0f;
            d = fminf(fmaxf(d, -one_m_eps), one_m_eps);
            float r = s_rp[i] / d;
            float mn = 2.0f * atanhf(r) * s_sign[i] + rw * s_msgs[k];
            s_msgs[k] = mn;
            atomicAdd(&s_bel[j], mn * mwde[k]);
        }
        __syncthreads();

        // phase 4: weighted BCE loss, block reduce
        float loc = 0.0f;
        for (int j = tid; j < Ndim; j += NTH) {
            float x = s_bel[j];
            float sp = fmaxf(x, 0.0f) + log1pf(expf(-fabsf(x)));
            loc += sp - s_err[j] * x;
        }
        for (int o = 16; o; o >>= 1) loc += __shfl_xor_sync(0xffffffffu, loc, o);
        if (lane == 0) s_red[wid] = loc;
        __syncthreads();
        if (wid == 0) {
            float v = s_red[lane];
            for (int o = 16; o; o >>= 1) v += __shfl_xor_sync(0xffffffffu, v, o);
            if (lane == 0) acc += g_rho[l] * v;
        }
        __syncthreads();
    }
    if (tid == 0) atomicAdd(out, acc * (1.0f / (float)Bsz));
}

// ---------------- host launcher ----------------
extern "C" void kernel_launch(void* const* d_in, const int* in_sizes, int n_in,
                              void* d_out, int out_size) {
    const int*   synd  = (const int*)d_in[0];    // (B,M,1) int32
    const int*   errs  = (const int*)d_in[1];    // (B,N)   int32
    const float* H     = (const float*)d_in[2];  // (M,N)
    const float* llrs  = (const float*)d_in[3];  // (N,)
    const float* wde   = (const float*)d_in[4];  // (L,M,N)
    const float* wllr  = (const float*)d_in[5];  // (L,N)
    const float* mwde  = (const float*)d_in[6];  // (L,M,N)
    const float* mwllr = (const float*)d_in[7];  // (L,N)
    const float* rhos  = (const float*)d_in[8];  // (L,)
    const float* resw  = (const float*)d_in[9];  // (L,)
    float* out = (float*)d_out;

    static int smem_set = 0;
    // idempotent; first (uncaptured) correctness call sets it before capture.
    cudaFuncSetAttribute(k_main, cudaFuncAttributeMaxDynamicSharedMemorySize, SMEM_BYTES);
    (void)smem_set;

    k_init<<<1, 32>>>(rhos, out);
    k_deg<<<Mdim, 256>>>(H);
    k_scan<<<1, Mdim>>>();
    k_fill<<<16, 1024>>>(H);
    k_gather<<<(Lnum * CAP + 1023) / 1024, 1024>>>(wde, mwde);
    k_main<<<Bsz, NTH, SMEM_BYTES>>>(synd, errs, llrs, wllr, mwllr, resw, out);
}

// round 2
// speedup vs baseline: 4.2738x; 4.2738x over previous
#include <cuda_runtime.h>
#include <cooperative_groups.h>
#include <math.h>

namespace cg = cooperative_groups;

#define Mdim 512
#define Ndim 2048
#define Bsz  4
#define Lnum 20
#define CAP  24576            // global nnz cap (E[nnz]=20971)
#define LCAP 6656             // per-CTA (128-row) entry cap (E=5243, +~19 sigma)
#define MNdim (Mdim*Ndim)
#define EPSV 1e-6f
#define NTH  1024
#define CLSZ 4                // CTAs per cluster (per batch)
#define ROWS_PER_CTA (Mdim/CLSZ)   // 128
#define COLS_PER_CTA (Ndim/CLSZ)   // 512

// ---------------- device scratch ----------------
__device__ int      g_deg[Mdim];
__device__ int      g_rowptr[Mdim + 1];
__device__ int      g_nnz;
__device__ unsigned g_lin[CAP];
__device__ float    g_wde[Lnum * CAP];
__device__ float    g_mwde[Lnum * CAP];
__device__ float    g_rho[Lnum];

// ---------------- K0: zero output + softmax(rhos) ----------------
__global__ void k_init(const float* __restrict__ rhos, float* __restrict__ out) {
    if (threadIdx.x == 0) {
        *out = 0.0f;
        float mx = -1e30f;
        for (int l = 0; l < Lnum; l++) mx = fmaxf(mx, rhos[l]);
        float e[Lnum], s = 0.0f;
        for (int l = 0; l < Lnum; l++) { e[l] = expf(rhos[l] - mx); s += e[l]; }
        float inv = 1.0f / s;
        for (int l = 0; l < Lnum; l++) g_rho[l] = e[l] * inv;
    }
}

// ---------------- K1: row degrees (block per row, float4) ----------------
__global__ void k_deg(const float4* __restrict__ H4) {
    __shared__ int red[8];
    int i = blockIdx.x;
    const float4* row = H4 + (size_t)i * (Ndim / 4);
    int cnt = 0;
    for (int c = threadIdx.x; c < Ndim / 4; c += 256) {
        float4 v = row[c];
        cnt += (v.x != 0.0f) + (v.y != 0.0f) + (v.z != 0.0f) + (v.w != 0.0f);
    }
    for (int o = 16; o; o >>= 1) cnt += __shfl_xor_sync(0xffffffffu, cnt, o);
    if ((threadIdx.x & 31) == 0) red[threadIdx.x >> 5] = cnt;
    __syncthreads();
    if (threadIdx.x == 0) {
        int s = 0;
        for (int w = 0; w < 8; w++) s += red[w];
        g_deg[i] = s;
    }
}

// ---------------- K2: exclusive scan of 512 degrees ----------------
__global__ void k_scan() {
    __shared__ int s[Mdim];
    int t = threadIdx.x;
    if (t < Mdim) s[t] = g_deg[t];
    __syncthreads();
    for (int off = 1; off < Mdim; off <<= 1) {
        int v = 0;
        if (t < Mdim && t >= off) v = s[t - off];
        __syncthreads();
        if (t < Mdim) s[t] += v;
        __syncthreads();
    }
    if (t < Mdim) g_rowptr[t + 1] = s[t];
    if (t == 0) g_rowptr[0] = 0;
    if (t == Mdim - 1) g_nnz = s[Mdim - 1];
}

// ---------------- K3: fill CSR linear indices (warp per row, float4) ----------------
__global__ void k_fill(const float4* __restrict__ H4) {
    int w = (blockIdx.x * blockDim.x + threadIdx.x) >> 5;
    int lane = threadIdx.x & 31;
    if (w >= Mdim) return;
    int base = g_rowptr[w];
    const float4* row = H4 + (size_t)w * (Ndim / 4);
    for (int c0 = 0; c0 < Ndim / 4; c0 += 32) {
        float4 v = row[c0 + lane];
        int cnt = (v.x != 0.0f) + (v.y != 0.0f) + (v.z != 0.0f) + (v.w != 0.0f);
        int sc = cnt;
        for (int o = 1; o < 32; o <<= 1) {
            int t = __shfl_up_sync(0xffffffffu, sc, o);
            if (lane >= o) sc += t;
        }
        int idx = base + (sc - cnt);
        int c = (c0 + lane) * 4;
        unsigned lb = (unsigned)(w * Ndim + c);
        if (v.x != 0.0f && idx < CAP) g_lin[idx++] = lb;
        if (v.y != 0.0f && idx < CAP) g_lin[idx++] = lb + 1;
        if (v.z != 0.0f && idx < CAP) g_lin[idx++] = lb + 2;
        if (v.w != 0.0f && idx < CAP) g_lin[idx++] = lb + 3;
        base += __shfl_sync(0xffffffffu, sc, 31);
    }
}

// ---------------- K4: gather dense weights at nonzeros ----------------
__global__ void k_gather(const float* __restrict__ wde, const float* __restrict__ mwde) {
    int nnz = min(g_nnz, CAP);
    int idx = blockIdx.x * blockDim.x + threadIdx.x;
    if (idx >= Lnum * CAP) return;
    int l = idx / CAP;
    int k = idx - l * CAP;
    if (k < nnz) {
        unsigned lin = g_lin[k];
        size_t off = (size_t)l * MNdim + lin;
        g_wde[idx]  = wde[off];
        g_mwde[idx] = mwde[off];
    }
}

// ---------------- K5: main BP recurrence (clustered, fused) ----------------
// smem: msgs LCAP f | colA N f | colB N f | belA N f | belB N f |
//       sign R f | off R f | err C f | lossacc 16f | rpt (R+1+3) i | lin LCAP u16
#define SMEM_BYTES ((LCAP + 4*Ndim + 2*ROWS_PER_CTA + COLS_PER_CTA + 16 + (ROWS_PER_CTA+4)) * 4 + LCAP * 2)

__global__ void __launch_bounds__(NTH, 1) __cluster_dims__(CLSZ, 1, 1)
k_main(const int*   __restrict__ synd,
       const int*   __restrict__ errs,
       const float* __restrict__ llrs,
       const float* __restrict__ wllr,
       const float* __restrict__ mwllr,
       const float* __restrict__ resw,
       float* __restrict__ out)
{
    extern __shared__ char sm_raw[];
    float*    s_msgs = (float*)sm_raw;                       // LCAP
    float*    s_colA = s_msgs + LCAP;                        // N
    float*    s_colB = s_colA + Ndim;                        // N
    float*    s_belA = s_colB + Ndim;                        // N
    float*    s_belB = s_belA + Ndim;                        // N
    float*    s_sign = s_belB + Ndim;                        // R
    float*    s_off  = s_sign + ROWS_PER_CTA;                // R
    float*    s_err  = s_off + ROWS_PER_CTA;                 // C
    float*    s_lacc = s_err + COLS_PER_CTA;                 // 16
    int*      s_rpt  = (int*)(s_lacc + 16);                  // R+1 (+pad)
    unsigned short* s_lin = (unsigned short*)(s_rpt + ROWS_PER_CTA + 4);  // LCAP

    cg::cluster_group cl = cg::this_cluster();
    const int rank = (int)cl.block_rank();
    const int b    = blockIdx.x / CLSZ;
    const int tid  = threadIdx.x;
    const int lane = tid & 31;
    const int wid  = tid >> 5;
    const float OME = 1.0f - EPSV;

    const int r0 = rank * ROWS_PER_CTA;
    const int kbase = g_rowptr[r0];
    int kend = g_rowptr[r0 + ROWS_PER_CTA];
    if (kend - kbase > LCAP) kend = kbase + LCAP;
    const int cnt = kend - kbase;

    // ---- prologue ----
    for (int k = tid; k < cnt; k += NTH) {
        s_lin[k]  = (unsigned short)(g_lin[kbase + k] & (Ndim - 1));
        s_msgs[k] = 0.0f;
    }
    if (tid <= ROWS_PER_CTA) s_rpt[tid] = g_rowptr[r0 + tid] - kbase;
    if (tid < ROWS_PER_CTA) {
        int row = r0 + tid;
        s_sign[tid] = 1.0f - 2.0f * (float)synd[b * Mdim + row];
        int d = g_rowptr[row + 1] - g_rowptr[row];
        s_off[tid] = powf(OME, (float)(Ndim - d));
    }
    if (tid < COLS_PER_CTA)
        s_err[tid] = 1.0f - (float)errs[b * Ndim + rank * COLS_PER_CTA + tid];
    for (int j = tid; j < Ndim; j += NTH) {
        s_colA[j] = llrs[j] * wllr[j];     // layer-0 combined column input
        s_colB[j] = 0.0f;
        s_belA[j] = 0.0f;
        s_belB[j] = 0.0f;
    }
    if (tid < 16) s_lacc[tid] = 0.0f;
    __syncthreads();

    float acc = 0.0f;
    for (int l = 0; l < Lnum; l++) {
        float* colR = (l & 1) ? s_colB : s_colA;   // combined, read
        float* colW = (l & 1) ? s_colA : s_colB;   // partial, accumulate
        float* belW = (l & 1) ? s_belB : s_belA;   // partial, accumulate
        const float rw = __ldg(&resw[l]);
        const float* mwde_l = &g_mwde[l * CAP + kbase];
        const float* wde_n  = (l + 1 < Lnum) ? &g_wde[(l + 1) * CAP + kbase] : mwde_l;
        const bool last = (l == Lnum - 1);

        // ---- pass: warp per row ----
        for (int rr = wid; rr < ROWS_PER_CTA; rr += 32) {
            int st = s_rpt[rr], en = s_rpt[rr + 1];
            float p = 1.0f;
            float dloc[4], wm[4], wn[4];
            int nit = 0;
            for (int k = st + lane; k < en; k += 32, nit++) {
                float men = colR[s_lin[k]] - s_msgs[k];
                float t = __expf(men);
                float d = __fdividef(t - 1.0f, t + 1.0f);   // tanh(men/2)
                if (d == 0.0f) d = 1.0f;
                d = fminf(fmaxf(d, -OME), OME);
                dloc[nit] = d;
                wm[nit] = mwde_l[k];
                wn[nit] = wde_n[k];
                p *= d;
            }
            for (int o = 16; o; o >>= 1) p *= __shfl_xor_sync(0xffffffffu, p, o);
            p *= s_off[rr];
            float sg = s_sign[rr];
            nit = 0;
            for (int k = st + lane; k < en; k += 32, nit++) {
                float d = dloc[nit];
                float r = __fdividef(p, d);
                float ath = (fabsf(r) < 6.25e-3f) ? r * (1.0f + (1.0f/3.0f) * r * r)
                                                  : atanhf(r);
                float mn = 2.0f * ath * sg + rw * s_msgs[k];
                s_msgs[k] = mn;
                int j = s_lin[k];
                atomicAdd(&belW[j], mn * wm[nit]);
                if (!last) atomicAdd(&colW[j], mn * wn[nit]);
            }
        }
        cl.sync();

        // ---- combine across cluster (slice-owned) ----
        if (tid < COLS_PER_CTA) {
            // column-sum combine + broadcast for next layer
            if (!last) {
                int j = rank * COLS_PER_CTA + tid;
                float s = llrs[j] * wllr[(l + 1) * Ndim + j];
                #pragma unroll
                for (int r = 0; r < CLSZ; r++)
                    s += ((float*)cl.map_shared_rank(colW, r))[j];
                #pragma unroll
                for (int r = 0; r < CLSZ; r++)
                    ((float*)cl.map_shared_rank(colW, r))[j] = s;
            }
        } else if (tid < 2 * COLS_PER_CTA) {
            // belief combine + BCE loss for this slice
            int jj = tid - COLS_PER_CTA;
            int j = rank * COLS_PER_CTA + jj;
            float x = llrs[j] * mwllr[l * Ndim + j];
            #pragma unroll
            for (int r = 0; r < CLSZ; r++)
                x += ((float*)cl.map_shared_rank(belW, r))[j];
            float sp = fmaxf(x, 0.0f) + log1pf(__expf(-fabsf(x)));
            acc += g_rho[l] * (sp - s_err[jj] * x);
        }
        // local resets: colR becomes next partial accumulator; other bel buffer
        {
            float* belZ = (l & 1) ? s_belA : s_belB;
            for (int j = tid; j < Ndim; j += NTH) {
                colR[j] = 0.0f;
                belZ[j] = 0.0f;
            }
        }
        cl.sync();
    }

    // ---- loss reduce (only threads [512, 1024) hold acc) ----
    for (int o = 16; o; o >>= 1) acc += __shfl_xor_sync(0xffffffffu, acc, o);
    if (wid >= 16 && lane == 0) s_lacc[wid - 16] = acc;
    __syncthreads();
    if (tid == 0) {
        float s = 0.0f;
        for (int w = 0; w < 16; w++) s += s_lacc[w];
        atomicAdd(out, s * (1.0f / (float)Bsz));
    }
}

// ---------------- host launcher ----------------
extern "C" void kernel_launch(void* const* d_in, const int* in_sizes, int n_in,
                              void* d_out, int out_size) {
    const int*   synd  = (const int*)d_in[0];
    const int*   errs  = (const int*)d_in[1];
    const float* H     = (const float*)d_in[2];
    const float* llrs  = (const float*)d_in[3];
    const float* wde   = (const float*)d_in[4];
    const float* wllr  = (const float*)d_in[5];
    const float* mwde  = (const float*)d_in[6];
    const float* mwllr = (const float*)d_in[7];
    const float* rhos  = (const float*)d_in[8];
    const float* resw  = (const float*)d_in[9];
    float* out = (float*)d_out;

    cudaFuncSetAttribute(k_main, cudaFuncAttributeMaxDynamicSharedMemorySize, SMEM_BYTES);

    k_init<<<1, 32>>>(rhos, out);
    k_deg<<<Mdim, 256>>>((const float4*)H);
    k_scan<<<1, Mdim>>>();
    k_fill<<<16, 1024>>>((const float4*)H);
    k_gather<<<(Lnum * CAP + 1023) / 1024, 1024>>>(wde, mwde);
    k_main<<<Bsz * CLSZ, NTH, SMEM_BYTES>>>(synd, errs, llrs, wllr, mwllr, resw, out);
}